// round 11
// baseline (speedup 1.0000x reference)
#include <cuda_runtime.h>
#include <cuda_bf16.h>

// x: (256,64,25,3) f32; W_conv: (3,192) f32; W_a: (128,1) f32; out: (256,3,25,25) f32
// Verified math (R1/R3/R7):
//   xbar[j] = sum_t x[n,t,j], j=v*3+i (1/64 folded into u)
//   u{1,2}[i,k] = (1/64) sum_c W_conv[i,c*3+k]*W_a[{0,64}+c]
//   s{1,2}[v,k] = sum_i xbar[v*3+i]*u{1,2}[i,k]
//   row(0..74), col q: e = s1[(row%3)*25+q] + s2[(row/3)*3 + ((row%3)+q)%3]
//   exp(leaky(e)) = max(E1[r]*E2[c], F1[r]*F2[c]), E=exp2(L2E*s), F=exp2(0.2*L2E*s)
// R11: 75 loader threads x 16 LDG.128; float4 t+75k shares its column-quadruple
//   for all k, so 16-way fold happens IN REGISTERS; smem partials 1200->300;
//   phase2 folds 4 slots (buf[c], c+75, c+150, c+225) with direct LDS (no shfl).

#define TPB 320

__device__ __forceinline__ unsigned long long add2(unsigned long long a, unsigned long long b) {
    unsigned long long r;
    asm("add.rn.f32x2 %0, %1, %2;" : "=l"(r) : "l"(a), "l"(b));
    return r;
}
__device__ __forceinline__ unsigned long long mul2(unsigned long long a, unsigned long long b) {
    unsigned long long r;
    asm("mul.rn.f32x2 %0, %1, %2;" : "=l"(r) : "l"(a), "l"(b));
    return r;
}
__device__ __forceinline__ unsigned long long pack2(float lo, float hi) {
    unsigned long long r;
    asm("mov.b64 %0, {%1, %2};" : "=l"(r) : "f"(lo), "f"(hi));
    return r;
}
__device__ __forceinline__ void unpack2(unsigned long long v, float &lo, float &hi) {
    asm("mov.b64 {%0, %1}, %2;" : "=f"(lo), "=f"(hi) : "l"(v));
}
__device__ __forceinline__ float ex2a(float x) {
    float r; asm("ex2.approx.f32 %0, %1;" : "=f"(r) : "f"(x)); return r;
}

__global__ __launch_bounds__(TPB)
void gat_adj_kernel(const float* __restrict__ x,
                    const float* __restrict__ Wc,
                    const float* __restrict__ Wa,
                    float* __restrict__ out)
{
    __shared__ __align__(16) float buf[304];            // 4 partial slots x 75 cols (+pad)
    __shared__ float uu[18];                            // [which*9+i*3+k], /64 folded
    __shared__ unsigned long long ep1[75], ep2[75];     // packed (E,F) per column

    const int n   = blockIdx.x;
    const int tid = threadIdx.x;

    if (tid < 75) {
        // ---- Loaders: 16 LDG.128 each (float4 idx tid+75k -> same col quad),
        //      full 16-way fold in registers, single STS.128 of the quad partial ----
        const ulonglong2* xg = reinterpret_cast<const ulonglong2*>(x) + (size_t)n * 1200;
        ulonglong2 v0  = xg[tid];
        ulonglong2 v1  = xg[tid + 75];
        ulonglong2 v2  = xg[tid + 150];
        ulonglong2 v3  = xg[tid + 225];
        ulonglong2 v4  = xg[tid + 300];
        ulonglong2 v5  = xg[tid + 375];
        ulonglong2 v6  = xg[tid + 450];
        ulonglong2 v7  = xg[tid + 525];
        ulonglong2 v8  = xg[tid + 600];
        ulonglong2 v9  = xg[tid + 675];
        ulonglong2 v10 = xg[tid + 750];
        ulonglong2 v11 = xg[tid + 825];
        ulonglong2 v12 = xg[tid + 900];
        ulonglong2 v13 = xg[tid + 975];
        ulonglong2 v14 = xg[tid + 1050];
        ulonglong2 v15 = xg[tid + 1125];
        ulonglong2 s;
        s.x = add2(add2(add2(v0.x, v1.x),  add2(v2.x, v3.x)),
                   add2(add2(v4.x, v5.x),  add2(v6.x, v7.x)));
        s.x = add2(s.x,
              add2(add2(add2(v8.x, v9.x),  add2(v10.x, v11.x)),
                   add2(add2(v12.x, v13.x), add2(v14.x, v15.x))));
        s.y = add2(add2(add2(v0.y, v1.y),  add2(v2.y, v3.y)),
                   add2(add2(v4.y, v5.y),  add2(v6.y, v7.y)));
        s.y = add2(s.y,
              add2(add2(add2(v8.y, v9.y),  add2(v10.y, v11.y)),
                   add2(add2(v12.y, v13.y), add2(v14.y, v15.y))));
        // partial for columns (4tid..4tid+3)%75 lands at buf[4tid..4tid+3]
        reinterpret_cast<ulonglong2*>(buf)[tid] = s;
    } else if (tid >= 96 && tid < 240) {
        // ---- u warps (dedicated): 18 outputs x 8 lanes x 8 terms ----
        const int idx = tid - 96;                       // 0..143
        const int o = idx >> 3;                         // 0..17
        const int p = idx & 7;
        const int which = o / 9;
        const int rem   = o % 9;
        const int i     = rem / 3;
        const int k     = rem % 3;
        const int c0    = p * 8;
        const float* wcb = Wc + i * 192 + k;
        const float4 wa0 = *reinterpret_cast<const float4*>(Wa + which * 64 + c0);
        const float4 wa1 = *reinterpret_cast<const float4*>(Wa + which * 64 + c0 + 4);
        float acc = wcb[(c0 + 0) * 3] * wa0.x + wcb[(c0 + 1) * 3] * wa0.y
                  + wcb[(c0 + 2) * 3] * wa0.z + wcb[(c0 + 3) * 3] * wa0.w
                  + wcb[(c0 + 4) * 3] * wa1.x + wcb[(c0 + 5) * 3] * wa1.y
                  + wcb[(c0 + 6) * 3] * wa1.z + wcb[(c0 + 7) * 3] * wa1.w;
        // warps 3-6 fully in u-range; warp 7 uses lanes 0..15 only
        const unsigned mask = (tid < 224) ? 0xFFFFFFFFu : 0x0000FFFFu;
        acc += __shfl_xor_sync(mask, acc, 1);
        acc += __shfl_xor_sync(mask, acc, 2);
        acc += __shfl_xor_sync(mask, acc, 4);
        if (p == 0) uu[o] = acc * (1.0f / 64.0f);
    }
    __syncthreads();   // bar 0

    // ---- Phase 2: 75 threads, direct 12-LDS fold (no shfl), scores + exps ----
    if (tid < 75) {
        const int k  = tid % 3;
        const int v3 = tid - k;
        const float a0 = ((buf[v3]     + buf[v3 + 75])  + (buf[v3 + 150] + buf[v3 + 225]));
        const float a1 = ((buf[v3 + 1] + buf[v3 + 76])  + (buf[v3 + 151] + buf[v3 + 226]));
        const float a2 = ((buf[v3 + 2] + buf[v3 + 77])  + (buf[v3 + 152] + buf[v3 + 227]));

        const float s1 = a0 * uu[k]     + a1 * uu[3 + k]  + a2 * uu[6 + k];
        const float s2 = a0 * uu[9 + k] + a1 * uu[12 + k] + a2 * uu[15 + k];
        const float L2E  = 1.4426950408889634f;
        const float L2E5 = 0.2f * L2E;
        const float E1 = ex2a(s1 * L2E),  F1 = ex2a(s1 * L2E5);
        const float E2 = ex2a(s2 * L2E),  F2 = ex2a(s2 * L2E5);
        ep1[tid] = pack2(E1, F1);
        ep2[tid] = pack2(E2, F2);
    }
    __syncthreads();   // bar 1

    // ---- Phase 3: softmax, 4 threads/row (verified map), MUFU-free hot loop ----
    {
        int row = tid >> 2;
        const bool act = (row < 75);
        if (row > 74) row = 74;                 // tid 300..319: safe duplicate work
        const int part = tid & 3;
        const int d  = row % 3;
        const int a3 = row - d;
        const int r0 = d * 25;

        const unsigned long long c0 = ep2[a3];
        const unsigned long long c1 = ep2[a3 + 1];
        const unsigned long long c2 = ep2[a3 + 2];

        const int qs  = (part == 0) ? 0 : part * 6 + 1;   // 0,7,13,19
        const int cnt = (part == 0) ? 7 : 6;

        const int kk0 = (d + qs) % 3;
        unsigned long long ra = (kk0 == 0) ? c0 : ((kk0 == 1) ? c1 : c2);
        unsigned long long rb = (kk0 == 0) ? c1 : ((kk0 == 1) ? c2 : c0);
        unsigned long long rc = (kk0 == 0) ? c2 : ((kk0 == 1) ? c0 : c1);

        float vals[7];
        float sum0 = 0.f, sum1 = 0.f;
        #pragma unroll
        for (int j = 0; j < 7; j++) {
            if (j < cnt) {
                const unsigned long long pr = mul2(ep1[r0 + qs + j], ra);
                float pe, pf;
                unpack2(pr, pe, pf);
                const float vl = fmaxf(pe, pf);   // exp2(leaky(e)) by monotonicity
                vals[j] = vl;
                if (j & 1) sum1 += vl; else sum0 += vl;
                unsigned long long t = ra; ra = rb; rb = rc; rc = t;
            }
        }
        float sum = sum0 + sum1;
        sum += __shfl_xor_sync(0xffffffffu, sum, 1);
        sum += __shfl_xor_sync(0xffffffffu, sum, 2);
        const float inv = __fdividef(1.0f, sum);

        if (act) {
            float* og = out + (size_t)n * 1875 + row * 25 + qs;
            #pragma unroll
            for (int j = 0; j < 7; j++)
                if (j < cnt) og[j] = vals[j] * inv;
        }
    }
}

extern "C" void kernel_launch(void* const* d_in, const int* in_sizes, int n_in,
                              void* d_out, int out_size)
{
    const float* x  = (const float*)d_in[0];
    const float* Wc = (const float*)d_in[1];
    const float* Wa = (const float*)d_in[2];
    float* out = (float*)d_out;
    gat_adj_kernel<<<256, TPB>>>(x, Wc, Wa, out);
}